// round 8
// baseline (speedup 1.0000x reference)
#include <cuda_runtime.h>
#include <math.h>
#include <stdint.h>

#define OBSD 194
#define HD   64
#define AD   5
#define ED   3
#define BLOCK 128
#define ROWS  64
#define NCH1  7
#define XSTR  40
#define XBUF  (ROWS * XSTR)          // 2560 floats per staging buffer
#define G1F   (NCH1 * 4096)
#define GTOT  (G1F + 2 * 4096)
#define PERM(j) ((j) < 4 ? 2*(j) : 2*(j) - 7)

__device__ __align__(16) float g_b[GTOT];

__device__ __forceinline__ float tf32r(float f) {
    uint32_t r; asm("cvt.rna.tf32.f32 %0, %1;" : "=r"(r) : "f"(f));
    return __uint_as_float(r);
}
__device__ __forceinline__ float tanha(float x) {
    float y; asm("tanh.approx.f32 %0, %1;" : "=f"(y) : "f"(x)); return y;
}
__device__ __forceinline__ void mma8(float* c, uint32_t a0, uint32_t a1, uint32_t a2,
                                     uint32_t a3, uint32_t b0, uint32_t b1) {
    asm volatile("mma.sync.aligned.m16n8k8.row.col.f32.tf32.tf32.f32 "
                 "{%0,%1,%2,%3},{%4,%5,%6,%7},{%8,%9},{%0,%1,%2,%3};"
                 : "+f"(c[0]), "+f"(c[1]), "+f"(c[2]), "+f"(c[3])
                 : "r"(a0), "r"(a1), "r"(a2), "r"(a3), "r"(b0), "r"(b1));
}
#define F2U(x) __float_as_uint(x)

// ---------- prep: bake B operands as float4-fragment images (tf32-rounded) ----------
__global__ void prep_b(const float* __restrict__ W1, const float* __restrict__ Wc1,
                       const float* __restrict__ W2, const float* __restrict__ Wc2) {
    int idx = blockIdx.x * blockDim.x + threadIdx.x;
    if (idx >= GTOT) return;
    int lane = (idx >> 2) & 31;
    int q    = idx & 3;
    int g = lane >> 2, tg = lane & 3;
    float v = 0.f;
    if (idx < G1F) {
        int c     = idx >> 12;
        int h     = (idx >> 11) & 1;
        int ntAll = (idx >> 7) & 15;
        int k8 = 2 * h + (q >> 1);
        int k  = 32 * c + 8 * k8 + tg + 4 * (q & 1);
        int n  = 8 * ntAll + g;
        if (k < OBSD) v = (n < HD) ? W1[k * HD + n] : Wc1[k * HD + n - HD];
    } else {
        int t     = idx - G1F;
        int mat   = t >> 12;
        int kh    = (t >> 11) & 1;
        int h     = (t >> 10) & 1;
        int ntAll = (t >> 7) & 7;
        int k8 = 2 * h + (q >> 1);
        int k  = 32 * kh + 8 * k8 + tg + 4 * (q & 1);
        int n  = 8 * ntAll + g;
        v = (mat ? Wc2 : W2)[k * HD + n];
    }
    g_b[idx] = tf32r(v);
}

// ---------- main: 128 threads, 64 samples/CTA, 4 CTAs/SM ----------
__global__ void __launch_bounds__(BLOCK, 4)
agent_mma(const float* __restrict__ x,   const int* __restrict__ action,
          const float* __restrict__ b1,  const float* __restrict__ b2,
          const float* __restrict__ Wh,  const float* __restrict__ bh,
          const float* __restrict__ bc1, const float* __restrict__ bc2,
          const float* __restrict__ Wc3, const float* __restrict__ bc3,
          float* __restrict__ out, int Bn)
{
    __shared__ __align__(16) float spool[2 * XBUF];   // two staging buffers (20KB)
    __shared__ float whs[ED * HD * AD];
    __shared__ float bhs[16];
    __shared__ float b1s[HD], b2s[HD], bc1s[HD], bc2s[HD], wc3s[HD];
    __shared__ float valbuf[2][ROWS];

    const float4* gb4 = (const float4*)g_b;

    const int tid   = threadIdx.x;
    const int lane  = tid & 31;
    const int warp  = tid >> 5;
    const int warpM = warp & 1;
    const int warpN = warp >> 1;
    const int g     = lane >> 2;
    const int tg    = lane & 3;
    const int rb2   = warpM * 32;
    const int s0    = blockIdx.x * ROWS;

    // x staging geometry: thread covers k = {2*kpair, 2*kpair+1}, rows rowb + 8*it
    const int kpair = tid & 15;
    const int rowb  = tid >> 4;                 // 0..7
    const int j0    = (2 * kpair) & 7;
    const int k80   = (2 * kpair) >> 3;
    const int o0    = k80 * 8 + PERM(j0);
    const int o1    = k80 * 8 + PERM(j0 + 1);
    // H staging perms
    const int p0 = PERM(2 * tg);
    const int p1 = PERM(2 * tg + 1);

    for (int i = tid; i < ED * HD * AD; i += BLOCK) whs[i] = Wh[i];
    if (tid < ED * AD) bhs[tid] = bh[tid];
    if (tid < HD) {
        b1s[tid] = b1[tid];   b2s[tid] = b2[tid];
        bc1s[tid] = bc1[tid]; bc2s[tid] = bc2[tid]; wc3s[tid] = Wc3[tid];
    }
    const float bc3v = __ldg(&bc3[0]);

    float acc[2][8][4];
    #pragma unroll
    for (int t = 0; t < 2; t++)
        #pragma unroll
        for (int nt = 0; nt < 8; nt++)
            #pragma unroll
            for (int i = 0; i < 4; i++) acc[t][nt][i] = 0.f;

    // stage chunk 0 into buf0
    {
        #pragma unroll
        for (int it = 0; it < 8; it++) {
            int row = rowb + 8 * it;
            int srow = s0 + row; if (srow >= Bn) srow = Bn - 1;
            float2 v = __ldg((const float2*)(x + (size_t)srow * OBSD + 2 * kpair));
            spool[row * XSTR + o0] = tf32r(v.x);
            spool[row * XSTR + o1] = tf32r(v.y);
        }
    }

    // ================= GEMM1: C[64x128] = X @ [W1|Wc1], 7 chunks =================
    for (int c = 0; c < NCH1; c++) {
        float2 xq[8];
        if (c < NCH1 - 1) {                 // prefetch next chunk's x
            int col0 = 32 * (c + 1) + 2 * kpair;
            #pragma unroll
            for (int it = 0; it < 8; it++) {
                int row = rowb + 8 * it;
                int srow = s0 + row; if (srow >= Bn) srow = Bn - 1;
                xq[it] = (col0 < OBSD)
                    ? __ldg((const float2*)(x + (size_t)srow * OBSD + col0))
                    : make_float2(0.f, 0.f);
            }
        }
        __syncthreads();                    // buf[c&1] ready for all warps

        const float2* xs2 = (const float2*)(spool + (c & 1) * XBUF);
        const float4* gbc = gb4 + c * 1024 + (warpN * 8) * 32 + lane;

        #pragma unroll
        for (int h = 0; h < 2; h++) {
            float2 aL[2][2], aH[2][2];
            #pragma unroll
            for (int t = 0; t < 2; t++)
                #pragma unroll
                for (int e = 0; e < 2; e++) {
                    int ko = (2 * h + e) * 4 + tg;
                    aL[t][e] = xs2[(rb2 + 16 * t + g)     * 20 + ko];
                    aH[t][e] = xs2[(rb2 + 16 * t + g + 8) * 20 + ko];
                }
            #pragma unroll
            for (int nt = 0; nt < 8; nt++) {
                float4 bq = __ldg(gbc + h * 512 + nt * 32);
                mma8(acc[0][nt], F2U(aL[0][0].x), F2U(aH[0][0].x),
                     F2U(aL[0][0].y), F2U(aH[0][0].y), F2U(bq.x), F2U(bq.y));
                mma8(acc[1][nt], F2U(aL[1][0].x), F2U(aH[1][0].x),
                     F2U(aL[1][0].y), F2U(aH[1][0].y), F2U(bq.x), F2U(bq.y));
                mma8(acc[0][nt], F2U(aL[0][1].x), F2U(aH[0][1].x),
                     F2U(aL[0][1].y), F2U(aH[0][1].y), F2U(bq.z), F2U(bq.w));
                mma8(acc[1][nt], F2U(aL[1][1].x), F2U(aH[1][1].x),
                     F2U(aL[1][1].y), F2U(aH[1][1].y), F2U(bq.z), F2U(bq.w));
            }
        }

        if (c < NCH1 - 1) {                 // stage next chunk into the other buffer
            float* xsn = spool + ((c + 1) & 1) * XBUF;
            #pragma unroll
            for (int it = 0; it < 8; it++) {
                int rbase = (rowb + 8 * it) * XSTR;
                xsn[rbase + o0] = tf32r(xq[it].x);
                xsn[rbase + o1] = tf32r(xq[it].y);
            }
        }
    }

    // epilogue1: bias + tanh (warpN0 = actor H cols, warpN1 = critic H cols)
    {
        const float* bA = warpN ? bc1s : b1s;
        #pragma unroll
        for (int t = 0; t < 2; t++)
            #pragma unroll
            for (int nt = 0; nt < 8; nt++) {
                int n0 = 8 * nt + 2 * tg;
                acc[t][nt][0] = tanha(acc[t][nt][0] + bA[n0]);
                acc[t][nt][1] = tanha(acc[t][nt][1] + bA[n0 + 1]);
                acc[t][nt][2] = tanha(acc[t][nt][2] + bA[n0]);
                acc[t][nt][3] = tanha(acc[t][nt][3] + bA[n0 + 1]);
            }
    }

    // ================= GEMM2: critic pass (mat=1) then actor pass (mat=0) =================
    #pragma unroll 1
    for (int pp = 0; pp < 2; pp++) {
        const int mat = (pp == 0) ? 1 : 0;
        float acc2[2][4][4];
        #pragma unroll
        for (int t = 0; t < 2; t++)
            #pragma unroll
            for (int nt = 0; nt < 4; nt++)
                #pragma unroll
                for (int i = 0; i < 4; i++) acc2[t][nt][i] = 0.f;

        __syncthreads();                    // buffers free for restaging
        if (warpN == mat) {                 // owner warps stage both kh chunks of H
            #pragma unroll
            for (int kh = 0; kh < 2; kh++) {
                float* xsn = spool + kh * XBUF;
                #pragma unroll
                for (int t = 0; t < 2; t++)
                    #pragma unroll
                    for (int q = 0; q < 4; q++) {
                        int ntsel = 4 * kh + q;
                        int r0 = (rb2 + 16 * t + g) * XSTR + q * 8;
                        int r1 = (rb2 + 16 * t + g + 8) * XSTR + q * 8;
                        xsn[r0 + p0] = tf32r(acc[t][ntsel][0]);
                        xsn[r0 + p1] = tf32r(acc[t][ntsel][1]);
                        xsn[r1 + p0] = tf32r(acc[t][ntsel][2]);
                        xsn[r1 + p1] = tf32r(acc[t][ntsel][3]);
                    }
            }
        }
        __syncthreads();

        const float4* gb2 = gb4 + (G1F >> 2) + mat * 1024 + (warpN * 4) * 32 + lane;
        #pragma unroll
        for (int kh = 0; kh < 2; kh++) {
            const float2* xs2 = (const float2*)(spool + kh * XBUF);
            #pragma unroll
            for (int h = 0; h < 2; h++) {
                float2 aL[2][2], aH[2][2];
                #pragma unroll
                for (int t = 0; t < 2; t++)
                    #pragma unroll
                    for (int e = 0; e < 2; e++) {
                        int ko = (2 * h + e) * 4 + tg;
                        aL[t][e] = xs2[(rb2 + 16 * t + g)     * 20 + ko];
                        aH[t][e] = xs2[(rb2 + 16 * t + g + 8) * 20 + ko];
                    }
                #pragma unroll
                for (int nt = 0; nt < 4; nt++) {
                    float4 bq = __ldg(gb2 + kh * 512 + h * 256 + nt * 32);
                    mma8(acc2[0][nt], F2U(aL[0][0].x), F2U(aH[0][0].x),
                         F2U(aL[0][0].y), F2U(aH[0][0].y), F2U(bq.x), F2U(bq.y));
                    mma8(acc2[1][nt], F2U(aL[1][0].x), F2U(aH[1][0].x),
                         F2U(aL[1][0].y), F2U(aH[1][0].y), F2U(bq.x), F2U(bq.y));
                    mma8(acc2[0][nt], F2U(aL[0][1].x), F2U(aH[0][1].x),
                         F2U(aL[0][1].y), F2U(aH[0][1].y), F2U(bq.z), F2U(bq.w));
                    mma8(acc2[1][nt], F2U(aL[1][1].x), F2U(aH[1][1].x),
                         F2U(aL[1][1].y), F2U(aH[1][1].y), F2U(bq.z), F2U(bq.w));
                }
            }
        }

        if (mat == 1) {
            float vr[4] = {0.f, 0.f, 0.f, 0.f};
            #pragma unroll
            for (int t = 0; t < 2; t++)
                #pragma unroll
                for (int nt = 0; nt < 4; nt++) {
                    int n0 = warpN * 32 + 8 * nt + 2 * tg;
                    vr[2*t]   = fmaf(tanha(acc2[t][nt][0] + bc2s[n0]),     wc3s[n0],     vr[2*t]);
                    vr[2*t]   = fmaf(tanha(acc2[t][nt][1] + bc2s[n0 + 1]), wc3s[n0 + 1], vr[2*t]);
                    vr[2*t+1] = fmaf(tanha(acc2[t][nt][2] + bc2s[n0]),     wc3s[n0],     vr[2*t+1]);
                    vr[2*t+1] = fmaf(tanha(acc2[t][nt][3] + bc2s[n0 + 1]), wc3s[n0 + 1], vr[2*t+1]);
                }
            #pragma unroll
            for (int i = 0; i < 4; i++) {
                vr[i] += __shfl_xor_sync(0xFFFFFFFF, vr[i], 1);
                vr[i] += __shfl_xor_sync(0xFFFFFFFF, vr[i], 2);
            }
            if (tg == 0) {                   // per-warpN partials; head combines
                valbuf[warpN][rb2 + g]      = vr[0];
                valbuf[warpN][rb2 + g + 8]  = vr[1];
                valbuf[warpN][rb2 + g + 16] = vr[2];
                valbuf[warpN][rb2 + g + 24] = vr[3];
            }
        } else {
            // actor: feat -> fbuf (stride 65), spool reuse
            __syncthreads();
            float* fbuf = spool;
            #pragma unroll
            for (int t = 0; t < 2; t++)
                #pragma unroll
                for (int nt = 0; nt < 4; nt++) {
                    int n0 = warpN * 32 + 8 * nt + 2 * tg;
                    int r0 = (rb2 + 16 * t + g) * 65;
                    int r1 = (rb2 + 16 * t + g + 8) * 65;
                    fbuf[r0 + n0]     = tanha(acc2[t][nt][0] + b2s[n0]);
                    fbuf[r0 + n0 + 1] = tanha(acc2[t][nt][1] + b2s[n0 + 1]);
                    fbuf[r1 + n0]     = tanha(acc2[t][nt][2] + b2s[n0]);
                    fbuf[r1 + n0 + 1] = tanha(acc2[t][nt][3] + b2s[n0 + 1]);
                }
            __syncthreads();
        }
    }

    // ================= per-sample head =================
    if (tid < ROWS) {
        const float* fbuf = spool;
        int s = s0 + tid;
        int sr = (s < Bn) ? s : (Bn - 1);
        const float* xrow = x + (size_t)sr * OBSD;
        float x0 = __ldg(&xrow[0]), x1v = __ldg(&xrow[1]), x2v = __ldg(&xrow[2]);
        int ev = 0; float bx = x0;
        if (x1v > bx) { bx = x1v; ev = 1; }
        if (x2v > bx) { ev = 2; }

        float lg[AD];
        #pragma unroll
        for (int a = 0; a < AD; a++) lg[a] = bhs[ev * AD + a];
        const float* fr  = &fbuf[tid * 65];
        const float* whe = &whs[ev * HD * AD];
        #pragma unroll 8
        for (int k = 0; k < HD; k++) {
            float fk = fr[k];
            #pragma unroll
            for (int a = 0; a < AD; a++) lg[a] = fmaf(fk, whe[k * AD + a], lg[a]);
        }
        float m = lg[0];
        #pragma unroll
        for (int a = 1; a < AD; a++) m = fmaxf(m, lg[a]);
        float se = 0.f;
        #pragma unroll
        for (int a = 0; a < AD; a++) se += __expf(lg[a] - m);
        float lse = __logf(se);
        float ent = 0.f;
        #pragma unroll
        for (int a = 0; a < AD; a++) {
            float lp = lg[a] - m - lse;
            ent -= __expf(lp) * lp;
        }
        int   act  = __ldg(&action[sr]);
        float logp = lg[act] - m - lse;

        if (s < Bn) {
            out[s]          = (float)act;
            out[Bn + s]     = logp;
            out[2 * Bn + s] = ent;
            out[3 * Bn + s] = valbuf[0][tid] + valbuf[1][tid] + bc3v;
        }
    }
}

extern "C" void kernel_launch(void* const* d_in, const int* in_sizes, int n_in,
                              void* d_out, int out_size) {
    const float* x    = (const float*)d_in[0];
    const int*   act  = (const int*)  d_in[1];
    const float* W1   = (const float*)d_in[2];
    const float* b1   = (const float*)d_in[3];
    const float* W2   = (const float*)d_in[4];
    const float* b2   = (const float*)d_in[5];
    const float* Wh   = (const float*)d_in[6];
    const float* bh   = (const float*)d_in[7];
    const float* Wc1  = (const float*)d_in[8];
    const float* bc1  = (const float*)d_in[9];
    const float* Wc2  = (const float*)d_in[10];
    const float* bc2  = (const float*)d_in[11];
    const float* Wc3  = (const float*)d_in[12];
    const float* bc3  = (const float*)d_in[13];
    float* out = (float*)d_out;

    const int Bn = in_sizes[1];

    prep_b<<<(GTOT + 255) / 256, 256>>>(W1, Wc1, W2, Wc2);

    const int grid = (Bn + ROWS - 1) / ROWS;
    agent_mma<<<grid, BLOCK>>>(x, act, b1, b2, Wh, bh, bc1, bc2, Wc3, bc3, out, Bn);
}

// round 9
// speedup vs baseline: 1.5292x; 1.5292x over previous
#include <cuda_runtime.h>
#include <cuda_fp16.h>
#include <math.h>
#include <stdint.h>

#define OBSD 194
#define HD   64
#define AD   5
#define ED   3
#define BLOCK 128
#define ROWS  64
#define NCH1  7
#define G1H   (NCH1 * 2048)          // GEMM1 B image, uint32 units
#define GTOT32 (G1H + 2 * 2048)      // + W2, Wc2 images

__device__ __align__(16) uint32_t g_b[GTOT32];

__device__ __forceinline__ uint32_t smem_u32(const void* p) {
    uint32_t a;
    asm("{ .reg .u64 t; cvta.to.shared.u64 t, %1; cvt.u32.u64 %0, t; }" : "=r"(a) : "l"(p));
    return a;
}
__device__ __forceinline__ float tanha(float x) {
    float y; asm("tanh.approx.f32 %0, %1;" : "=f"(y) : "f"(x)); return y;
}
__device__ __forceinline__ void mma16(float* c, uint32_t a0, uint32_t a1, uint32_t a2,
                                      uint32_t a3, uint32_t b0, uint32_t b1) {
    asm volatile("mma.sync.aligned.m16n8k16.row.col.f32.f16.f16.f32 "
                 "{%0,%1,%2,%3},{%4,%5,%6,%7},{%8,%9},{%0,%1,%2,%3};"
                 : "+f"(c[0]), "+f"(c[1]), "+f"(c[2]), "+f"(c[3])
                 : "r"(a0), "r"(a1), "r"(a2), "r"(a3), "r"(b0), "r"(b1));
}
__device__ __forceinline__ void ldsm4(uint32_t* r, uint32_t addr) {
    asm volatile("ldmatrix.sync.aligned.m8n8.x4.shared.b16 {%0,%1,%2,%3}, [%4];"
                 : "=r"(r[0]), "=r"(r[1]), "=r"(r[2]), "=r"(r[3]) : "r"(addr));
}
__device__ __forceinline__ uint32_t pack_h2(float lo, float hi) {
    half2 h = __floats2half2_rn(lo, hi);
    return *reinterpret_cast<uint32_t*>(&h);
}

// ---------- prep: bake fp16 B fragment images ----------
// GEMM1 u32 idx = c*2048 + f*1024 + np*128 + lane*4 + q
//   ntAll = np*2 + (q>>1), r = q&1; k_lo = 32c+16f+2tg+8r; n = 8*ntAll+g; [W1|Wc1]
// GEMM2 u32 idx = G1H + mat*2048 + kf*512 + np*128 + lane*4 + q  (W2, Wc2; K=64)
__global__ void prep_b(const float* __restrict__ W1, const float* __restrict__ Wc1,
                       const float* __restrict__ W2, const float* __restrict__ Wc2) {
    int idx = blockIdx.x * blockDim.x + threadIdx.x;
    if (idx >= GTOT32) return;
    int lane = (idx >> 2) & 31;
    int q    = idx & 3;
    int g = lane >> 2, tg = lane & 3;
    int r = q & 1;
    float lo = 0.f, hi = 0.f;
    if (idx < G1H) {
        int c     = idx >> 11;
        int f     = (idx >> 10) & 1;
        int np    = (idx >> 7) & 7;
        int ntAll = np * 2 + (q >> 1);
        int k0 = 32 * c + 16 * f + 2 * tg + 8 * r;
        int n  = 8 * ntAll + g;
        if (k0 < OBSD)     lo = (n < HD) ? W1[k0 * HD + n]       : Wc1[k0 * HD + n - HD];
        if (k0 + 1 < OBSD) hi = (n < HD) ? W1[(k0 + 1) * HD + n] : Wc1[(k0 + 1) * HD + n - HD];
    } else {
        int t   = idx - G1H;
        int mat = t >> 11;
        int kf  = (t >> 9) & 3;
        int np  = (t >> 7) & 3;
        int ntAll = np * 2 + (q >> 1);
        int k0 = 16 * kf + 2 * tg + 8 * r;
        int n  = 8 * ntAll + g;
        const float* Wm = mat ? Wc2 : W2;
        lo = Wm[k0 * HD + n];
        hi = Wm[(k0 + 1) * HD + n];
    }
    half2 h = __floats2half2_rn(lo, hi);
    g_b[idx] = *reinterpret_cast<uint32_t*>(&h);
}

// ---------- main: 128 threads, 64 samples/CTA, 4 CTAs/SM ----------
// smem A layout per 4KB buffer: 32 tiles of 128B; tile(rg,kg) at (rg*4+kg)*128B;
// row j of tile stored at rotated slot ((j + 2*kg) & 7) * 16B  (conflict-free STS + LDSM)
__global__ void __launch_bounds__(BLOCK, 4)
agent_mma(const float* __restrict__ x,   const int* __restrict__ action,
          const float* __restrict__ b1,  const float* __restrict__ b2,
          const float* __restrict__ Wh,  const float* __restrict__ bh,
          const float* __restrict__ bc1, const float* __restrict__ bc2,
          const float* __restrict__ Wc3, const float* __restrict__ bc3,
          float* __restrict__ out, int Bn)
{
    __shared__ __align__(16) float spool[4160];   // 2x 4KB A-buffers; reused as fbuf (16.6KB)
    __shared__ float whs[ED * HD * AD];
    __shared__ float bhs[16];
    __shared__ float b1s[HD], b2s[HD], bc1s[HD], bc2s[HD], wc3s[HD];
    __shared__ float valbuf[2][ROWS];

    uint32_t* sp32 = (uint32_t*)spool;
    const uint4* gb4 = (const uint4*)g_b;
    const uint32_t sbase = smem_u32(spool);

    const int tid   = threadIdx.x;
    const int lane  = tid & 31;
    const int warp  = tid >> 5;
    const int warpM = warp & 1;
    const int warpN = warp >> 1;
    const int g     = lane >> 2;
    const int tg    = lane & 3;
    const int rb2   = warpM * 32;
    const int s0    = blockIdx.x * ROWS;

    // x staging geometry: thread covers k = {2*kpair, 2*kpair+1}, rows rowb + 8*it
    const int kpair = tid & 15;
    const int rowb  = tid >> 4;                 // 0..7
    const int kg_st = kpair >> 2;
    const int kw_st = kpair & 3;
    const int perm_st = ((rowb + 2 * kg_st) & 7);
    const int woff_st = kg_st * 32 + perm_st * 4 + kw_st;  // + it*128 per row-group

    for (int i = tid; i < ED * HD * AD; i += BLOCK) whs[i] = Wh[i];
    if (tid < ED * AD) bhs[tid] = bh[tid];
    if (tid < HD) {
        b1s[tid] = b1[tid];   b2s[tid] = b2[tid];
        bc1s[tid] = bc1[tid]; bc2s[tid] = bc2[tid]; wc3s[tid] = Wc3[tid];
    }
    const float bc3v = __ldg(&bc3[0]);

    float acc[2][8][4];
    #pragma unroll
    for (int t = 0; t < 2; t++)
        #pragma unroll
        for (int nt = 0; nt < 8; nt++)
            #pragma unroll
            for (int i = 0; i < 4; i++) acc[t][nt][i] = 0.f;

    // stage chunk 0 into buf0
    #pragma unroll
    for (int it = 0; it < 8; it++) {
        int row = rowb + 8 * it;
        int srow = s0 + row; if (srow >= Bn) srow = Bn - 1;
        float2 v = __ldg((const float2*)(x + (size_t)srow * OBSD + 2 * kpair));
        sp32[it * 128 + woff_st] = pack_h2(v.x, v.y);
    }

    // ================= GEMM1: C[64x128] = X @ [W1|Wc1], 7 chunks =================
    for (int c = 0; c < NCH1; c++) {
        float2 xq[8];
        if (c < NCH1 - 1) {
            int col0 = 32 * (c + 1) + 2 * kpair;
            #pragma unroll
            for (int it = 0; it < 8; it++) {
                int row = rowb + 8 * it;
                int srow = s0 + row; if (srow >= Bn) srow = Bn - 1;
                xq[it] = (col0 < OBSD)
                    ? __ldg((const float2*)(x + (size_t)srow * OBSD + col0))
                    : make_float2(0.f, 0.f);
            }
        }
        __syncthreads();

        const uint32_t bufaddr = sbase + (c & 1) * 4096;
        #pragma unroll
        for (int f = 0; f < 2; f++) {
            uint32_t A[2][4];
            #pragma unroll
            for (int t = 0; t < 2; t++) {
                int mi = lane >> 3;
                int rg = 4 * warpM + 2 * t + (mi & 1);
                int kg = 2 * f + (mi >> 1);
                int rowp = ((lane & 7) + 2 * kg) & 7;
                ldsm4(A[t], bufaddr + (rg * 4 + kg) * 128 + rowp * 16);
            }
            #pragma unroll
            for (int npi = 0; npi < 4; npi++) {
                uint4 bq = __ldg(&gb4[c * 512 + f * 256 + warpN * 128 + npi * 32 + lane]);
                mma16(acc[0][2*npi],   A[0][0], A[0][1], A[0][2], A[0][3], bq.x, bq.y);
                mma16(acc[1][2*npi],   A[1][0], A[1][1], A[1][2], A[1][3], bq.x, bq.y);
                mma16(acc[0][2*npi+1], A[0][0], A[0][1], A[0][2], A[0][3], bq.z, bq.w);
                mma16(acc[1][2*npi+1], A[1][0], A[1][1], A[1][2], A[1][3], bq.z, bq.w);
            }
        }

        if (c < NCH1 - 1) {
            uint32_t* bn = sp32 + ((c + 1) & 1) * 1024;
            #pragma unroll
            for (int it = 0; it < 8; it++)
                bn[it * 128 + woff_st] = pack_h2(xq[it].x, xq[it].y);
        }
    }

    // epilogue1: bias + tanh (warpN0 = actor H, warpN1 = critic H)
    {
        const float* bA = warpN ? bc1s : b1s;
        #pragma unroll
        for (int t = 0; t < 2; t++)
            #pragma unroll
            for (int nt = 0; nt < 8; nt++) {
                int n0 = 8 * nt + 2 * tg;
                acc[t][nt][0] = tanha(acc[t][nt][0] + bA[n0]);
                acc[t][nt][1] = tanha(acc[t][nt][1] + bA[n0 + 1]);
                acc[t][nt][2] = tanha(acc[t][nt][2] + bA[n0]);
                acc[t][nt][3] = tanha(acc[t][nt][3] + bA[n0 + 1]);
            }
    }

    // ================= GEMM2: critic pass (mat=1) then actor pass (mat=0) =================
    #pragma unroll 1
    for (int pp = 0; pp < 2; pp++) {
        const int mat = (pp == 0) ? 1 : 0;
        float acc2[2][4][4];
        #pragma unroll
        for (int t = 0; t < 2; t++)
            #pragma unroll
            for (int nt = 0; nt < 4; nt++)
                #pragma unroll
                for (int i = 0; i < 4; i++) acc2[t][nt][i] = 0.f;

        __syncthreads();
        if (warpN == mat) {                 // owner warps stage H (both kh buffers)
            #pragma unroll
            for (int t = 0; t < 2; t++)
                #pragma unroll
                for (int nt = 0; nt < 8; nt++) {
                    int kh = nt >> 2, kg = nt & 3;
                    uint32_t* buf = sp32 + kh * 1024;
                    int perm = (g + 2 * kg) & 7;
                    int rga = 4 * warpM + 2 * t;
                    buf[(rga * 4 + kg) * 32 + perm * 4 + tg] =
                        pack_h2(acc[t][nt][0], acc[t][nt][1]);
                    buf[((rga + 1) * 4 + kg) * 32 + perm * 4 + tg] =
                        pack_h2(acc[t][nt][2], acc[t][nt][3]);
                }
        }
        __syncthreads();

        #pragma unroll
        for (int kh = 0; kh < 2; kh++) {
            const uint32_t bufaddr = sbase + kh * 4096;
            #pragma unroll
            for (int f = 0; f < 2; f++) {
                uint32_t A[2][4];
                #pragma unroll
                for (int t = 0; t < 2; t++) {
                    int mi = lane >> 3;
                    int rg = 4 * warpM + 2 * t + (mi & 1);
                    int kg = 2 * f + (mi >> 1);
                    int rowp = ((lane & 7) + 2 * kg) & 7;
                    ldsm4(A[t], bufaddr + (rg * 4 + kg) * 128 + rowp * 16);
                }
                int kf = kh * 2 + f;
                #pragma unroll
                for (int npi = 0; npi < 2; npi++) {
                    uint4 bq = __ldg(&gb4[G1H/4 + mat * 512 + kf * 128
                                          + warpN * 64 + npi * 32 + lane]);
                    mma16(acc2[0][2*npi],   A[0][0], A[0][1], A[0][2], A[0][3], bq.x, bq.y);
                    mma16(acc2[1][2*npi],   A[1][0], A[1][1], A[1][2], A[1][3], bq.x, bq.y);
                    mma16(acc2[0][2*npi+1], A[0][0], A[0][1], A[0][2], A[0][3], bq.z, bq.w);
                    mma16(acc2[1][2*npi+1], A[1][0], A[1][1], A[1][2], A[1][3], bq.z, bq.w);
                }
            }
        }

        if (mat == 1) {
            float vr[4] = {0.f, 0.f, 0.f, 0.f};
            #pragma unroll
            for (int t = 0; t < 2; t++)
                #pragma unroll
                for (int nt = 0; nt < 4; nt++) {
                    int n0 = warpN * 32 + 8 * nt + 2 * tg;
                    vr[2*t]   = fmaf(tanha(acc2[t][nt][0] + bc2s[n0]),     wc3s[n0],     vr[2*t]);
                    vr[2*t]   = fmaf(tanha(acc2[t][nt][1] + bc2s[n0 + 1]), wc3s[n0 + 1], vr[2*t]);
                    vr[2*t+1] = fmaf(tanha(acc2[t][nt][2] + bc2s[n0]),     wc3s[n0],     vr[2*t+1]);
                    vr[2*t+1] = fmaf(tanha(acc2[t][nt][3] + bc2s[n0 + 1]), wc3s[n0 + 1], vr[2*t+1]);
                }
            #pragma unroll
            for (int i = 0; i < 4; i++) {
                vr[i] += __shfl_xor_sync(0xFFFFFFFF, vr[i], 1);
                vr[i] += __shfl_xor_sync(0xFFFFFFFF, vr[i], 2);
            }
            if (tg == 0) {
                valbuf[warpN][rb2 + g]      = vr[0];
                valbuf[warpN][rb2 + g + 8]  = vr[1];
                valbuf[warpN][rb2 + g + 16] = vr[2];
                valbuf[warpN][rb2 + g + 24] = vr[3];
            }
        } else {
            __syncthreads();
            float* fbuf = spool;     // 64 x 65 fp32
            #pragma unroll
            for (int t = 0; t < 2; t++)
                #pragma unroll
                for (int nt = 0; nt < 4; nt++) {
                    int n0 = warpN * 32 + 8 * nt + 2 * tg;
                    int r0 = (rb2 + 16 * t + g) * 65;
                    int r1 = (rb2 + 16 * t + g + 8) * 65;
                    fbuf[r0 + n0]     = tanha(acc2[t][nt][0] + b2s[n0]);
                    fbuf[r0 + n0 + 1] = tanha(acc2[t][nt][1] + b2s[n0 + 1]);
                    fbuf[r1 + n0]     = tanha(acc2[t][nt][2] + b2s[n0]);
                    fbuf[r1 + n0 + 1] = tanha(acc2[t][nt][3] + b2s[n0 + 1]);
                }
            __syncthreads();
        }
    }

    // ================= per-sample head =================
    if (tid < ROWS) {
        const float* fbuf = spool;
        int s = s0 + tid;
        int sr = (s < Bn) ? s : (Bn - 1);
        const float* xrow = x + (size_t)sr * OBSD;
        float x0 = __ldg(&xrow[0]), x1v = __ldg(&xrow[1]), x2v = __ldg(&xrow[2]);
        int ev = 0; float bx = x0;
        if (x1v > bx) { bx = x1v; ev = 1; }
        if (x2v > bx) { ev = 2; }

        float lg[AD];
        #pragma unroll
        for (int a = 0; a < AD; a++) lg[a] = bhs[ev * AD + a];
        const float* fr  = &fbuf[tid * 65];
        const float* whe = &whs[ev * HD * AD];
        #pragma unroll 8
        for (int k = 0; k < HD; k++) {
            float fk = fr[k];
            #pragma unroll
            for (int a = 0; a < AD; a++) lg[a] = fmaf(fk, whe[k * AD + a], lg[a]);
        }
        float m = lg[0];
        #pragma unroll
        for (int a = 1; a < AD; a++) m = fmaxf(m, lg[a]);
        float se = 0.f;
        #pragma unroll
        for (int a = 0; a < AD; a++) se += __expf(lg[a] - m);
        float lse = __logf(se);
        float ent = 0.f;
        #pragma unroll
        for (int a = 0; a < AD; a++) {
            float lp = lg[a] - m - lse;
            ent -= __expf(lp) * lp;
        }
        int   act  = __ldg(&action[sr]);
        float logp = lg[act] - m - lse;

        if (s < Bn) {
            out[s]          = (float)act;
            out[Bn + s]     = logp;
            out[2 * Bn + s] = ent;
            out[3 * Bn + s] = valbuf[0][tid] + valbuf[1][tid] + bc3v;
        }
    }
}

extern "C" void kernel_launch(void* const* d_in, const int* in_sizes, int n_in,
                              void* d_out, int out_size) {
    const float* x    = (const float*)d_in[0];
    const int*   act  = (const int*)  d_in[1];
    const float* W1   = (const float*)d_in[2];
    const float* b1   = (const float*)d_in[3];
    const float* W2   = (const float*)d_in[4];
    const float* b2   = (const float*)d_in[5];
    const float* Wh   = (const float*)d_in[6];
    const float* bh   = (const float*)d_in[7];
    const float* Wc1  = (const float*)d_in[8];
    const float* bc1  = (const float*)d_in[9];
    const float* Wc2  = (const float*)d_in[10];
    const float* bc2  = (const float*)d_in[11];
    const float* Wc3  = (const float*)d_in[12];
    const float* bc3  = (const float*)d_in[13];
    float* out = (float*)d_out;

    const int Bn = in_sizes[1];

    prep_b<<<(GTOT32 + 255) / 256, 256>>>(W1, Wc1, W2, Wc2);

    const int grid = (Bn + ROWS - 1) / ROWS;
    agent_mma<<<grid, BLOCK>>>(x, act, b1, b2, Wh, bh, bc1, bc2, Wc3, bc3, out, Bn);
}